// round 14
// baseline (speedup 1.0000x reference)
#include <cuda_runtime.h>
#include <cuda_fp16.h>
#include <cstdint>

// ---------------------------------------------------------------------------
// Problem constants
// ---------------------------------------------------------------------------
#define D_DIM 128
#define O_DIM 128
#define R_DIM 4
#define N_MAX 100000

// Scratch
__device__ __half g_Yh[(size_t)R_DIM * N_MAX * O_DIM];   // Y fp16 [R][N][O]
__device__ __half g_WhT[(size_t)R_DIM * O_DIM * D_DIM];  // W^T fp16 [R][O][D]

// ---------------------------------------------------------------------------
// Pre-pass: W[r*128+d][o] -> WhT[r][o][d], fp16, smem tile transpose
// ---------------------------------------------------------------------------
__global__ void __launch_bounds__(1024)
convert_Wt(const float* __restrict__ W)
{
    __shared__ float s[32][33];
    const int r  = blockIdx.y;
    const int td = (blockIdx.x >> 2) * 32;
    const int to = (blockIdx.x & 3) * 32;
    const int tx = threadIdx.x & 31;
    const int ty = threadIdx.x >> 5;
    s[ty][tx] = W[(size_t)(r * D_DIM + td + ty) * O_DIM + to + tx];
    __syncthreads();
    g_WhT[(size_t)r * O_DIM * D_DIM + (size_t)(to + ty) * D_DIM + td + tx] =
        __float2half_rn(s[tx][ty]);
}

// ---------------------------------------------------------------------------
// GEMM: per CTA 128 M-rows x 128 out-cols, ONE relation per launch.
// ---------------------------------------------------------------------------
#define SM_A 0
#define SM_B 32768
#define SMEM_TOTAL 65536

__device__ __forceinline__ uint32_t smem_u32(const void* p) {
    uint32_t a;
    asm("{ .reg .u64 t; cvta.to.shared.u64 t, %1; cvt.u32.u64 %0, t; }" : "=r"(a) : "l"(p));
    return a;
}
__device__ __forceinline__ uint32_t offAB(int row, int k) {
    return (uint32_t)row * 256u + (uint32_t)(((k >> 3) ^ (row & 7)) * 16) + (uint32_t)((k & 7) * 2);
}
__device__ __forceinline__ void ldsm4(uint32_t* r, uint32_t addr) {
    asm volatile("ldmatrix.sync.aligned.m8n8.x4.shared.b16 {%0,%1,%2,%3}, [%4];"
                 : "=r"(r[0]), "=r"(r[1]), "=r"(r[2]), "=r"(r[3]) : "r"(addr));
}
__device__ __forceinline__ void mma16816(float* c, const uint32_t* a, uint32_t b0, uint32_t b1) {
    asm volatile("mma.sync.aligned.m16n8k16.row.col.f32.f16.f16.f32 "
                 "{%0,%1,%2,%3}, {%4,%5,%6,%7}, {%8,%9}, {%0,%1,%2,%3};"
                 : "+f"(c[0]), "+f"(c[1]), "+f"(c[2]), "+f"(c[3])
                 : "r"(a[0]), "r"(a[1]), "r"(a[2]), "r"(a[3]), "r"(b0), "r"(b1));
}

__global__ void __launch_bounds__(256, 2)
gemm_fp16(const float* __restrict__ x, int N, int r)
{
    extern __shared__ char smem[];
    const uint32_t sb = smem_u32(smem);
    const int tid    = threadIdx.x;
    const int lane   = tid & 31;
    const int wid    = tid >> 5;
    const int warp_m = wid >> 2;
    const int warp_n = wid & 3;
    const int m0     = blockIdx.x * 128;

    // ---- fill B from WhT (LDG.128 -> swizzled STS.128) ----
    {
        const __half* Wt = g_WhT + (size_t)r * O_DIM * D_DIM;
#pragma unroll
        for (int i = 0; i < 8; i++) {
            int t   = tid + i * 256;
            int row = t >> 4;
            int c   = t & 15;
            uint32_t dsw = (uint32_t)row * 256u + (uint32_t)((c ^ (row & 7)) * 16);
            uint4 vb = *reinterpret_cast<const uint4*>(Wt + (size_t)row * D_DIM + c * 8);
            *reinterpret_cast<uint4*>(smem + SM_B + dsw) = vb;
        }
    }
    // ---- fill A from x (fp32 LDG.128 -> cvt -> swizzled STS.64) ----
    {
#pragma unroll
        for (int i = 0; i < 16; i++) {
            int idx = tid + i * 256;
            int row = idx >> 5;
            int f4  = idx & 31;
            int gm  = m0 + row;
            int gmc = (gm < N) ? gm : (N - 1);
            float4 v = *reinterpret_cast<const float4*>(x + (size_t)gmc * D_DIM + f4 * 4);
            __half2 h01 = __floats2half2_rn(v.x, v.y);
            __half2 h23 = __floats2half2_rn(v.z, v.w);
            uint2 pk = make_uint2(*reinterpret_cast<uint32_t*>(&h01),
                                  *reinterpret_cast<uint32_t*>(&h23));
            *reinterpret_cast<uint2*>(smem + SM_A + offAB(row, f4 * 4)) = pk;
        }
    }
    __syncthreads();

    // ---- MMA mainloop (single fp16 pass, K=128) ----
    float acc[4][4][4];
#pragma unroll
    for (int mt = 0; mt < 4; mt++)
#pragma unroll
        for (int nt = 0; nt < 4; nt++)
#pragma unroll
            for (int q = 0; q < 4; q++) acc[mt][nt][q] = 0.f;

    const int a_row = warp_m * 64 + (lane & 15);
    const int b_row = warp_n * 32 + (lane & 15);
    const int khalf = (lane >> 4) * 8;
    const uint32_t As = sb + SM_A, Bs = sb + SM_B;

#pragma unroll
    for (int ks = 0; ks < 8; ks++) {
        const int k0 = ks * 16;
        uint32_t a[4][4], b[2][4];
#pragma unroll
        for (int mt = 0; mt < 4; mt++)
            ldsm4(a[mt], As + offAB(a_row + mt * 16, k0 + khalf));
#pragma unroll
        for (int np = 0; np < 2; np++)
            ldsm4(b[np], Bs + offAB(b_row + np * 16, k0 + khalf));
#pragma unroll
        for (int mt = 0; mt < 4; mt++) {
#pragma unroll
            for (int nt = 0; nt < 4; nt++) {
                const uint32_t* bb = b[nt >> 1];
                uint32_t b0 = (nt & 1) ? bb[1] : bb[0];
                uint32_t b1 = (nt & 1) ? bb[3] : bb[2];
                mma16816(acc[mt][nt], a[mt], b0, b1);
            }
        }
    }

    // ---- epilogue: fp16 stores to Y ----
    __half* Yr = g_Yh + (size_t)r * N_MAX * O_DIM;
#pragma unroll
    for (int mt = 0; mt < 4; mt++) {
        int gm0 = m0 + warp_m * 64 + mt * 16 + (lane >> 2);
#pragma unroll
        for (int nt = 0; nt < 4; nt++) {
            int o = warp_n * 32 + nt * 8 + (lane & 3) * 2;
            if (gm0 < N) {
                __half2 h = __floats2half2_rn(acc[mt][nt][0], acc[mt][nt][1]);
                *reinterpret_cast<uint32_t*>(Yr + (size_t)gm0 * O_DIM + o) =
                    *reinterpret_cast<uint32_t*>(&h);
            }
            if (gm0 + 8 < N) {
                __half2 h = __floats2half2_rn(acc[mt][nt][2], acc[mt][nt][3]);
                *reinterpret_cast<uint32_t*>(Yr + (size_t)(gm0 + 8) * O_DIM + o) =
                    *reinterpret_cast<uint32_t*>(&h);
            }
        }
    }
}

// ---------------------------------------------------------------------------
// Scatter: out[row,:] += val * Y_r[col,:]  (ONE relation per launch)
// ---------------------------------------------------------------------------
__global__ __launch_bounds__(256)
void scatter_kernel(const int* __restrict__ rows, const int* __restrict__ cols,
                    const float* __restrict__ vals, float* __restrict__ out,
                    int E, int r)
{
    const int lane = threadIdx.x & 31;
    const int warp = (blockIdx.x * blockDim.x + threadIdx.x) >> 5;
    const int nwarps = (gridDim.x * blockDim.x) >> 5;

    const int*   __restrict__ rr = rows + (size_t)r * E;
    const int*   __restrict__ cc = cols + (size_t)r * E;
    const float* __restrict__ vv = vals + (size_t)r * E;
    const __half* __restrict__ Yr = g_Yh + (size_t)r * N_MAX * O_DIM;

    const int pairs = E >> 1;
    for (int p = warp; p < pairs; p += nwarps) {
        int e0 = 2 * p, e1 = 2 * p + 1;
        int   row0 = __ldg(rr + e0), row1 = __ldg(rr + e1);
        int   col0 = __ldg(cc + e0), col1 = __ldg(cc + e1);
        float v0   = __ldg(vv + e0), v1   = __ldg(vv + e1);

        uint2 q0 = *reinterpret_cast<const uint2*>(Yr + (size_t)col0 * O_DIM + lane * 4);
        uint2 q1 = *reinterpret_cast<const uint2*>(Yr + (size_t)col1 * O_DIM + lane * 4);

        __half2 a0 = *reinterpret_cast<__half2*>(&q0.x);
        __half2 a1 = *reinterpret_cast<__half2*>(&q0.y);
        __half2 b0 = *reinterpret_cast<__half2*>(&q1.x);
        __half2 b1 = *reinterpret_cast<__half2*>(&q1.y);
        float2 fa0 = __half22float2(a0), fa1 = __half22float2(a1);
        float2 fb0 = __half22float2(b0), fb1 = __half22float2(b1);

        float* d0 = out + (size_t)row0 * O_DIM + lane * 4;
        float* d1 = out + (size_t)row1 * O_DIM + lane * 4;
        asm volatile("red.global.add.v4.f32 [%0], {%1, %2, %3, %4};"
                     :: "l"(d0), "f"(fa0.x * v0), "f"(fa0.y * v0),
                        "f"(fa1.x * v0), "f"(fa1.y * v0) : "memory");
        asm volatile("red.global.add.v4.f32 [%0], {%1, %2, %3, %4};"
                     :: "l"(d1), "f"(fb0.x * v1), "f"(fb0.y * v1),
                        "f"(fb1.x * v1), "f"(fb1.y * v1) : "memory");
    }
    if ((E & 1) && warp == 0) {
        int e = E - 1;
        int   row = __ldg(rr + e);
        int   col = __ldg(cc + e);
        float v   = __ldg(vv + e);
        uint2 q = *reinterpret_cast<const uint2*>(Yr + (size_t)col * O_DIM + lane * 4);
        __half2 h0 = *reinterpret_cast<__half2*>(&q.x);
        __half2 h1 = *reinterpret_cast<__half2*>(&q.y);
        float2 f0 = __half22float2(h0);
        float2 f1 = __half22float2(h1);
        float* dst = out + (size_t)row * O_DIM + lane * 4;
        asm volatile("red.global.add.v4.f32 [%0], {%1, %2, %3, %4};"
                     :: "l"(dst), "f"(f0.x * v), "f"(f0.y * v),
                        "f"(f1.x * v), "f"(f1.y * v) : "memory");
    }
}

// ---------------------------------------------------------------------------
// kernel_launch — fork-join overlap (retry of R13; R11 proved this failure
// mode can be pure infra flake). gemms on capture stream; memset+scatters on
// a non-blocking side stream gated per-relation by events; join before return.
// ---------------------------------------------------------------------------
extern "C" void kernel_launch(void* const* d_in, const int* in_sizes, int n_in,
                              void* d_out, int out_size)
{
    const float* x        = (const float*)d_in[0];
    const int*   edge_row = (const int*)  d_in[1];
    const int*   edge_col = (const int*)  d_in[2];
    const float* edge_val = (const float*)d_in[3];
    const float* W        = (const float*)d_in[4];
    float*       out      = (float*)d_out;

    const int N = in_sizes[0] / D_DIM;          // 100000
    const int E = in_sizes[1] / R_DIM;          // 400000

    cudaFuncSetAttribute(gemm_fp16, cudaFuncAttributeMaxDynamicSharedMemorySize, SMEM_TOTAL);

    cudaStream_t s1;
    cudaStreamCreateWithFlags(&s1, cudaStreamNonBlocking);
    cudaEvent_t evFork, evJoin, evG[R_DIM];
    cudaEventCreateWithFlags(&evFork, cudaEventDisableTiming);
    cudaEventCreateWithFlags(&evJoin, cudaEventDisableTiming);
    for (int r = 0; r < R_DIM; r++)
        cudaEventCreateWithFlags(&evG[r], cudaEventDisableTiming);

    // Fork side stream off the capture (default) stream.
    cudaEventRecord(evFork, 0);
    cudaStreamWaitEvent(s1, evFork, 0);

    // Side stream: zero out (required before any scatter).
    cudaMemsetAsync(out, 0, (size_t)out_size * sizeof(float), s1);

    // Main stream: W transpose, then per-relation GEMMs with completion events.
    {
        dim3 gw(16, R_DIM);
        convert_Wt<<<gw, 1024>>>(W);
    }
    const int mtiles = (N + 127) / 128;
    for (int r = 0; r < R_DIM; r++) {
        gemm_fp16<<<mtiles, 256, SMEM_TOTAL>>>(x, N, r);
        cudaEventRecord(evG[r], 0);
    }

    // Side stream: scatter(r) as soon as gemm(r) completes — overlaps gemm(r+1..).
    for (int r = 0; r < R_DIM; r++) {
        cudaStreamWaitEvent(s1, evG[r], 0);
        scatter_kernel<<<1024, 256, 0, s1>>>(edge_row, edge_col, edge_val, out, E, r);
    }

    // Join side stream back into the capture stream.
    cudaEventRecord(evJoin, s1);
    cudaStreamWaitEvent(0, evJoin, 0);
}

// round 16
// speedup vs baseline: 1.1795x; 1.1795x over previous
#include <cuda_runtime.h>
#include <cuda_fp16.h>
#include <cstdint>

// ---------------------------------------------------------------------------
// Problem constants
// ---------------------------------------------------------------------------
#define D_DIM 128
#define O_DIM 128
#define R_DIM 4
#define N_MAX 100000

// Scratch
__device__ __half g_Yh[(size_t)R_DIM * N_MAX * O_DIM];   // Y fp16 [R][N][O]
__device__ __half g_WhT[(size_t)R_DIM * O_DIM * D_DIM];  // W^T fp16 [R][O][D]

// ---------------------------------------------------------------------------
// Pre-pass: W[r*128+d][o] -> WhT[r][o][d], fp16, smem tile transpose
// ---------------------------------------------------------------------------
__global__ void __launch_bounds__(1024)
convert_Wt(const float* __restrict__ W)
{
    __shared__ float s[32][33];
    const int r  = blockIdx.y;
    const int td = (blockIdx.x >> 2) * 32;
    const int to = (blockIdx.x & 3) * 32;
    const int tx = threadIdx.x & 31;
    const int ty = threadIdx.x >> 5;
    s[ty][tx] = W[(size_t)(r * D_DIM + td + ty) * O_DIM + to + tx];
    __syncthreads();
    g_WhT[(size_t)r * O_DIM * D_DIM + (size_t)(to + ty) * D_DIM + td + tx] =
        __float2half_rn(s[tx][ty]);
}

// ---------------------------------------------------------------------------
// GEMM: per CTA 128 M-rows x 128 out-cols (one relation). Fused grid with
// relation as the FAST block index -> x tile reused in L2 across relations.
// ---------------------------------------------------------------------------
#define SM_A 0
#define SM_B 32768
#define SMEM_TOTAL 65536

__device__ __forceinline__ uint32_t smem_u32(const void* p) {
    uint32_t a;
    asm("{ .reg .u64 t; cvta.to.shared.u64 t, %1; cvt.u32.u64 %0, t; }" : "=r"(a) : "l"(p));
    return a;
}
__device__ __forceinline__ uint32_t offAB(int row, int k) {
    return (uint32_t)row * 256u + (uint32_t)(((k >> 3) ^ (row & 7)) * 16) + (uint32_t)((k & 7) * 2);
}
__device__ __forceinline__ void ldsm4(uint32_t* r, uint32_t addr) {
    asm volatile("ldmatrix.sync.aligned.m8n8.x4.shared.b16 {%0,%1,%2,%3}, [%4];"
                 : "=r"(r[0]), "=r"(r[1]), "=r"(r[2]), "=r"(r[3]) : "r"(addr));
}
__device__ __forceinline__ void mma16816(float* c, const uint32_t* a, uint32_t b0, uint32_t b1) {
    asm volatile("mma.sync.aligned.m16n8k16.row.col.f32.f16.f16.f32 "
                 "{%0,%1,%2,%3}, {%4,%5,%6,%7}, {%8,%9}, {%0,%1,%2,%3};"
                 : "+f"(c[0]), "+f"(c[1]), "+f"(c[2]), "+f"(c[3])
                 : "r"(a[0]), "r"(a[1]), "r"(a[2]), "r"(a[3]), "r"(b0), "r"(b1));
}

__global__ void __launch_bounds__(256, 2)
gemm_fp16(const float* __restrict__ x, int N)
{
    extern __shared__ char smem[];
    const uint32_t sb = smem_u32(smem);
    const int tid    = threadIdx.x;
    const int lane   = tid & 31;
    const int wid    = tid >> 5;
    const int warp_m = wid >> 2;
    const int warp_n = wid & 3;
    const int r      = blockIdx.x;        // relation fastest -> x L2 reuse
    const int m0     = blockIdx.y * 128;

    // ---- fill B from WhT (LDG.128 -> swizzled STS.128) ----
    {
        const __half* Wt = g_WhT + (size_t)r * O_DIM * D_DIM;
#pragma unroll
        for (int i = 0; i < 8; i++) {
            int t   = tid + i * 256;
            int row = t >> 4;
            int c   = t & 15;
            uint32_t dsw = (uint32_t)row * 256u + (uint32_t)((c ^ (row & 7)) * 16);
            uint4 vb = *reinterpret_cast<const uint4*>(Wt + (size_t)row * D_DIM + c * 8);
            *reinterpret_cast<uint4*>(smem + SM_B + dsw) = vb;
        }
    }
    // ---- fill A from x (fp32 LDG.128 -> cvt -> swizzled STS.64) ----
    {
#pragma unroll
        for (int i = 0; i < 16; i++) {
            int idx = tid + i * 256;
            int row = idx >> 5;
            int f4  = idx & 31;
            int gm  = m0 + row;
            int gmc = (gm < N) ? gm : (N - 1);
            float4 v = *reinterpret_cast<const float4*>(x + (size_t)gmc * D_DIM + f4 * 4);
            __half2 h01 = __floats2half2_rn(v.x, v.y);
            __half2 h23 = __floats2half2_rn(v.z, v.w);
            uint2 pk = make_uint2(*reinterpret_cast<uint32_t*>(&h01),
                                  *reinterpret_cast<uint32_t*>(&h23));
            *reinterpret_cast<uint2*>(smem + SM_A + offAB(row, f4 * 4)) = pk;
        }
    }
    __syncthreads();

    // ---- MMA mainloop (single fp16 pass, K=128) ----
    float acc[4][4][4];
#pragma unroll
    for (int mt = 0; mt < 4; mt++)
#pragma unroll
        for (int nt = 0; nt < 4; nt++)
#pragma unroll
            for (int q = 0; q < 4; q++) acc[mt][nt][q] = 0.f;

    const int a_row = warp_m * 64 + (lane & 15);
    const int b_row = warp_n * 32 + (lane & 15);
    const int khalf = (lane >> 4) * 8;
    const uint32_t As = sb + SM_A, Bs = sb + SM_B;

#pragma unroll
    for (int ks = 0; ks < 8; ks++) {
        const int k0 = ks * 16;
        uint32_t a[4][4], b[2][4];
#pragma unroll
        for (int mt = 0; mt < 4; mt++)
            ldsm4(a[mt], As + offAB(a_row + mt * 16, k0 + khalf));
#pragma unroll
        for (int np = 0; np < 2; np++)
            ldsm4(b[np], Bs + offAB(b_row + np * 16, k0 + khalf));
#pragma unroll
        for (int mt = 0; mt < 4; mt++) {
#pragma unroll
            for (int nt = 0; nt < 4; nt++) {
                const uint32_t* bb = b[nt >> 1];
                uint32_t b0 = (nt & 1) ? bb[1] : bb[0];
                uint32_t b1 = (nt & 1) ? bb[3] : bb[2];
                mma16816(acc[mt][nt], a[mt], b0, b1);
            }
        }
    }

    // ---- epilogue: fp16 stores to Y ----
    __half* Yr = g_Yh + (size_t)r * N_MAX * O_DIM;
#pragma unroll
    for (int mt = 0; mt < 4; mt++) {
        int gm0 = m0 + warp_m * 64 + mt * 16 + (lane >> 2);
#pragma unroll
        for (int nt = 0; nt < 4; nt++) {
            int o = warp_n * 32 + nt * 8 + (lane & 3) * 2;
            if (gm0 < N) {
                __half2 h = __floats2half2_rn(acc[mt][nt][0], acc[mt][nt][1]);
                *reinterpret_cast<uint32_t*>(Yr + (size_t)gm0 * O_DIM + o) =
                    *reinterpret_cast<uint32_t*>(&h);
            }
            if (gm0 + 8 < N) {
                __half2 h = __floats2half2_rn(acc[mt][nt][2], acc[mt][nt][3]);
                *reinterpret_cast<uint32_t*>(Yr + (size_t)(gm0 + 8) * O_DIM + o) =
                    *reinterpret_cast<uint32_t*>(&h);
            }
        }
    }
}

// ---------------------------------------------------------------------------
// Scatter: out[row,:] += val * Y_r[col,:]
// 4-edge unroll: four independent gathers in flight before the four red.v4.
// ---------------------------------------------------------------------------
__global__ __launch_bounds__(256)
void scatter_kernel(const int* __restrict__ rows, const int* __restrict__ cols,
                    const float* __restrict__ vals, float* __restrict__ out,
                    int E)
{
    const int r    = blockIdx.y;
    const int lane = threadIdx.x & 31;
    const int warp = (blockIdx.x * blockDim.x + threadIdx.x) >> 5;
    const int nwarps = (gridDim.x * blockDim.x) >> 5;

    const int*   __restrict__ rr = rows + (size_t)r * E;
    const int*   __restrict__ cc = cols + (size_t)r * E;
    const float* __restrict__ vv = vals + (size_t)r * E;
    const __half* __restrict__ Yr = g_Yh + (size_t)r * N_MAX * O_DIM;

    const int quads = E >> 2;
    for (int p = warp; p < quads; p += nwarps) {
        int e = 4 * p;
        int   row0 = __ldg(rr + e),     row1 = __ldg(rr + e + 1);
        int   row2 = __ldg(rr + e + 2), row3 = __ldg(rr + e + 3);
        int   col0 = __ldg(cc + e),     col1 = __ldg(cc + e + 1);
        int   col2 = __ldg(cc + e + 2), col3 = __ldg(cc + e + 3);
        float v0   = __ldg(vv + e),     v1   = __ldg(vv + e + 1);
        float v2   = __ldg(vv + e + 2), v3   = __ldg(vv + e + 3);

        uint2 q0 = *reinterpret_cast<const uint2*>(Yr + (size_t)col0 * O_DIM + lane * 4);
        uint2 q1 = *reinterpret_cast<const uint2*>(Yr + (size_t)col1 * O_DIM + lane * 4);
        uint2 q2 = *reinterpret_cast<const uint2*>(Yr + (size_t)col2 * O_DIM + lane * 4);
        uint2 q3 = *reinterpret_cast<const uint2*>(Yr + (size_t)col3 * O_DIM + lane * 4);

        float2 a0 = __half22float2(*reinterpret_cast<__half2*>(&q0.x));
        float2 a1 = __half22float2(*reinterpret_cast<__half2*>(&q0.y));
        float2 b0 = __half22float2(*reinterpret_cast<__half2*>(&q1.x));
        float2 b1 = __half22float2(*reinterpret_cast<__half2*>(&q1.y));
        float2 c0 = __half22float2(*reinterpret_cast<__half2*>(&q2.x));
        float2 c1 = __half22float2(*reinterpret_cast<__half2*>(&q2.y));
        float2 d0f = __half22float2(*reinterpret_cast<__half2*>(&q3.x));
        float2 d1f = __half22float2(*reinterpret_cast<__half2*>(&q3.y));

        float* d0 = out + (size_t)row0 * O_DIM + lane * 4;
        float* d1 = out + (size_t)row1 * O_DIM + lane * 4;
        float* d2 = out + (size_t)row2 * O_DIM + lane * 4;
        float* d3 = out + (size_t)row3 * O_DIM + lane * 4;
        asm volatile("red.global.add.v4.f32 [%0], {%1, %2, %3, %4};"
                     :: "l"(d0), "f"(a0.x * v0), "f"(a0.y * v0),
                        "f"(a1.x * v0), "f"(a1.y * v0) : "memory");
        asm volatile("red.global.add.v4.f32 [%0], {%1, %2, %3, %4};"
                     :: "l"(d1), "f"(b0.x * v1), "f"(b0.y * v1),
                        "f"(b1.x * v1), "f"(b1.y * v1) : "memory");
        asm volatile("red.global.add.v4.f32 [%0], {%1, %2, %3, %4};"
                     :: "l"(d2), "f"(c0.x * v2), "f"(c0.y * v2),
                        "f"(c1.x * v2), "f"(c1.y * v2) : "memory");
        asm volatile("red.global.add.v4.f32 [%0], {%1, %2, %3, %4};"
                     :: "l"(d3), "f"(d0f.x * v3), "f"(d0f.y * v3),
                        "f"(d1f.x * v3), "f"(d1f.y * v3) : "memory");
    }
    // tail (E % 4 edges): warps 0..2 handle one edge each
    const int tail0 = quads * 4;
    if (warp < (E - tail0)) {
        int e = tail0 + warp;
        int   row = __ldg(rr + e);
        int   col = __ldg(cc + e);
        float v   = __ldg(vv + e);
        uint2 q = *reinterpret_cast<const uint2*>(Yr + (size_t)col * O_DIM + lane * 4);
        float2 f0 = __half22float2(*reinterpret_cast<__half2*>(&q.x));
        float2 f1 = __half22float2(*reinterpret_cast<__half2*>(&q.y));
        float* dst = out + (size_t)row * O_DIM + lane * 4;
        asm volatile("red.global.add.v4.f32 [%0], {%1, %2, %3, %4};"
                     :: "l"(dst), "f"(f0.x * v), "f"(f0.y * v),
                        "f"(f1.x * v), "f"(f1.y * v) : "memory");
    }
}

// ---------------------------------------------------------------------------
// kernel_launch — single stream (R12 structure; overlap proven harmful R14)
// ---------------------------------------------------------------------------
extern "C" void kernel_launch(void* const* d_in, const int* in_sizes, int n_in,
                              void* d_out, int out_size)
{
    const float* x        = (const float*)d_in[0];
    const int*   edge_row = (const int*)  d_in[1];
    const int*   edge_col = (const int*)  d_in[2];
    const float* edge_val = (const float*)d_in[3];
    const float* W        = (const float*)d_in[4];
    float*       out      = (float*)d_out;

    const int N = in_sizes[0] / D_DIM;          // 100000
    const int E = in_sizes[1] / R_DIM;          // 400000

    cudaFuncSetAttribute(gemm_fp16, cudaFuncAttributeMaxDynamicSharedMemorySize, SMEM_TOTAL);

    cudaMemsetAsync(out, 0, (size_t)out_size * sizeof(float), 0);

    // Dense phase
    {
        dim3 gw(16, R_DIM);
        convert_Wt<<<gw, 1024>>>(W);
        dim3 grid(R_DIM, (N + 127) / 128);
        gemm_fp16<<<grid, 256, SMEM_TOTAL>>>(x, N);
    }
    // Sparse phase
    {
        dim3 grid(1024, R_DIM);
        scatter_kernel<<<grid, 256>>>(edge_row, edge_col, edge_val, out, E);
    }
}